// round 2
// baseline (speedup 1.0000x reference)
#include <cuda_runtime.h>
#include <cstdint>

#define DINL __device__ __forceinline__

// ---------------------------------------------------------------------------
// Precomputed weights in mma-fragment-friendly layouts (tf32-rounded fp32).
// g_w1p: GEMM1 A-operand = W_eff^T [256 x 800] as [kt(25)][ks(4)][mf(16)][r(8)][q(4)] float4
//        float4 = ( WT[n][k], WT[n+8][k], WT[n][k+4], WT[n+8][k+4] ),
//        n = mf*16+r, k = kt*32+ks*8+q.   (mma m16n8k8 A-frag ordering)
// g_w2p: GEMM2 A-operand = w2^T [128 x 256] as [ks(32)][mf(8)][r(8)][q(4)] float4
// g_w3p: GEMM3 A-operand = w3^T padded [16 x 128] as [ks(16)][r(8)][q(4)] float4
// ---------------------------------------------------------------------------
__device__ float4 g_w1p[25 * 4 * 16 * 8 * 4];   // 51200 float4
__device__ float4 g_w2p[32 * 8 * 8 * 4];        //  8192 float4
__device__ float4 g_w3p[16 * 8 * 4];            //   512 float4

DINL float tf32f(float f) { uint32_t u; asm("cvt.rna.tf32.f32 %0, %1;" : "=r"(u) : "f"(f)); return __uint_as_float(u); }
DINL uint32_t tf32u(float f) { uint32_t u; asm("cvt.rna.tf32.f32 %0, %1;" : "=r"(u) : "f"(f)); return u; }

DINL void mma8(float* c, uint32_t a0, uint32_t a1, uint32_t a2, uint32_t a3,
               uint32_t b0, uint32_t b1) {
    asm volatile(
        "mma.sync.aligned.m16n8k8.row.col.f32.tf32.tf32.f32 "
        "{%0,%1,%2,%3}, {%4,%5,%6,%7}, {%8,%9}, {%0,%1,%2,%3};"
        : "+f"(c[0]), "+f"(c[1]), "+f"(c[2]), "+f"(c[3])
        : "r"(a0), "r"(a1), "r"(a2), "r"(a3), "r"(b0), "r"(b1));
}

DINL void cpa16(uint32_t dst, const void* src) {
    asm volatile("cp.async.cg.shared.global [%0], [%1], 16;" :: "r"(dst), "l"(src));
}
DINL void cpa16z(uint32_t dst, const void* src) {
    asm volatile("cp.async.cg.shared.global [%0], [%1], 16, %2;" :: "r"(dst), "l"(src), "r"(0));
}

// ---------------------------------------------------------------------------
// Prep kernel: fold conv into fc1, transpose + tf32-round all weights.
// ---------------------------------------------------------------------------
DINL float weff(int k, int n, const float* cw, const float* w1) {
    if (k >= 784) return 0.f;
    int r = k / 28, c = k % 28;
    float acc = 0.f;
#pragma unroll
    for (int dr = 0; dr < 3; dr++)
#pragma unroll
        for (int dc = 0; dc < 3; dc++) {
            int rr = r - dr, cc = c - dc;
            if (rr >= 0 && rr < 26 && cc >= 0 && cc < 26)
                acc += cw[dr * 3 + dc] * w1[(rr * 26 + cc) * 256 + n];
        }
    return tf32f(acc);
}

__global__ __launch_bounds__(256) void prep_kernel(
    const float* __restrict__ cw, const float* __restrict__ w1,
    const float* __restrict__ w2, const float* __restrict__ w3) {
    int gid = blockIdx.x * 256 + threadIdx.x;
    if (blockIdx.x < 200) {
        int i = gid;                                    // 0..51199
        int q = i & 3, r = (i >> 2) & 7, mf = (i >> 5) & 15, ks = (i >> 9) & 3, kt = i >> 11;
        int k = kt * 32 + ks * 8 + q, n = mf * 16 + r;
        float4 v;
        v.x = weff(k, n, cw, w1);     v.y = weff(k, n + 8, cw, w1);
        v.z = weff(k + 4, n, cw, w1); v.w = weff(k + 4, n + 8, cw, w1);
        g_w1p[i] = v;
    } else if (blockIdx.x < 232) {
        int i = gid - 200 * 256;                        // 0..8191
        int q = i & 3, r = (i >> 2) & 7, mf = (i >> 5) & 7, ks = i >> 8;
        int k = ks * 8 + q, n = mf * 16 + r;
        float4 v;
        v.x = tf32f(w2[k * 128 + n]);       v.y = tf32f(w2[k * 128 + n + 8]);
        v.z = tf32f(w2[(k + 4) * 128 + n]); v.w = tf32f(w2[(k + 4) * 128 + n + 8]);
        g_w2p[i] = v;
    } else {
        int i = gid - 232 * 256;                        // 0..511
        if (i < 512) {
            int q = i & 3, r = (i >> 2) & 7, ks = i >> 5;
            int k = ks * 8 + q;
            float4 v;
            v.x = tf32f(w3[k * 10 + r]);
            v.y = (r + 8 < 10) ? tf32f(w3[k * 10 + r + 8]) : 0.f;
            v.z = tf32f(w3[(k + 4) * 10 + r]);
            v.w = (r + 8 < 10) ? tf32f(w3[(k + 4) * 10 + r + 8]) : 0.f;
            g_w3p[i] = v;
        }
    }
}

// ---------------------------------------------------------------------------
// Fused main kernel. Per CTA: 128 batch rows. Batch = N operand of mma.
// smem (floats):
//   phase A (aliased with h1T): x tiles 2x[128][36]  (0..9215)
//                               w1p tiles 2x8192     (9216..25599)
//   h1T [256][136]  at 0      (34816 floats)
//   h2T [128][136]  at 34816  (17408 floats)
//   w3p (512 f4)    at 52224  (2048 floats)
//   b1/b2/b3        at 54272 / 54528 / 54656
// ---------------------------------------------------------------------------
constexpr int XS = 36, H1S = 136, H2S = 136;
constexpr int OFF_X = 0;
constexpr int XBUF = 128 * XS;            // 4608
constexpr int OFF_W = 2 * XBUF;           // 9216
constexpr int WBUF = 8192;
constexpr int OFF_H1 = 0;
constexpr int OFF_H2 = 256 * H1S;         // 34816
constexpr int OFF_W3 = OFF_H2 + 128 * H2S;// 52224
constexpr int OFF_B1 = OFF_W3 + 2048;     // 54272
constexpr int OFF_B2 = OFF_B1 + 256;      // 54528
constexpr int OFF_B3 = OFF_B2 + 128;      // 54656
constexpr int SMEM_FLOATS = OFF_B3 + 16;  // 54672  (~214 KB)

__global__ __launch_bounds__(512, 1) void fused_kernel(
    const float* __restrict__ x, const float* __restrict__ b1,
    const float* __restrict__ b2, const float* __restrict__ b3,
    float* __restrict__ out) {
    extern __shared__ float smf[];
    const int tid = threadIdx.x, w = tid >> 5, lane = tid & 31;
    const int g = lane >> 2, q = lane & 3;
    const int m0 = blockIdx.x * 128;
    const uint32_t smb = (uint32_t)__cvta_generic_to_shared(smf);

    // phase 0: biases + w3 frags into smem
    if (tid < 256) smf[OFF_B1 + tid] = b1[tid];
    if (tid < 128) smf[OFF_B2 + tid] = b2[tid];
    if (tid < 16)  smf[OFF_B3 + tid] = (tid < 10) ? b3[tid] : 0.f;
    ((float4*)(smf + OFF_W3))[tid] = g_w3p[tid];

    auto issue = [&](int t, int buf) {
        const char* wsrc = (const char*)g_w1p + (size_t)t * 32768;
        uint32_t wdst = smb + (uint32_t)(OFF_W + buf * WBUF) * 4u;
#pragma unroll
        for (int i = 0; i < 4; i++) {
            int idx = tid + i * 512;
            cpa16(wdst + idx * 16, wsrc + idx * 16);
        }
#pragma unroll
        for (int i = 0; i < 2; i++) {
            int idx = tid + i * 512;
            int row = idx >> 3, p = idx & 7, kk = t * 32 + p * 4;
            uint32_t dst = smb + (uint32_t)(OFF_X + buf * XBUF + row * XS + p * 4) * 4u;
            const float* src = x + (size_t)(m0 + row) * 784 + kk;
            if (kk < 784) cpa16(dst, src);
            else          cpa16z(dst, x);
        }
        asm volatile("cp.async.commit_group;");
    };

    issue(0, 0);
    issue(1, 1);

    const int wm = w >> 2, wn = w & 3;

    // ---------------- GEMM1: [256 n1] x [784 k] x [128 b] ----------------
    float acc[4][4][4];
#pragma unroll
    for (int a = 0; a < 4; a++)
#pragma unroll
        for (int b = 0; b < 4; b++)
#pragma unroll
            for (int c = 0; c < 4; c++) acc[a][b][c] = 0.f;

    for (int t = 0; t < 25; t++) {
        if (t < 24) asm volatile("cp.async.wait_group 1;");
        else        asm volatile("cp.async.wait_group 0;");
        __syncthreads();
        const int buf = t & 1;
        const float* Xb = smf + OFF_X + buf * XBUF;
        const float4* Wb = (const float4*)(smf + OFF_W + buf * WBUF);
#pragma unroll
        for (int s = 0; s < 4; s++) {
            uint32_t a[4][4];
#pragma unroll
            for (int mf = 0; mf < 4; mf++) {
                float4 v = Wb[((s * 16 + wm * 4 + mf) * 8 + g) * 4 + q];
                a[mf][0] = __float_as_uint(v.x); a[mf][1] = __float_as_uint(v.y);
                a[mf][2] = __float_as_uint(v.z); a[mf][3] = __float_as_uint(v.w);
            }
            uint32_t bb[4][2];
#pragma unroll
            for (int nf = 0; nf < 4; nf++) {
                int bc = wn * 32 + nf * 8 + g;
                int k = s * 8 + q;
                bb[nf][0] = tf32u(Xb[bc * XS + k]);
                bb[nf][1] = tf32u(Xb[bc * XS + k + 4]);
            }
#pragma unroll
            for (int mf = 0; mf < 4; mf++)
#pragma unroll
                for (int nf = 0; nf < 4; nf++)
                    mma8(acc[mf][nf], a[mf][0], a[mf][1], a[mf][2], a[mf][3],
                         bb[nf][0], bb[nf][1]);
        }
        __syncthreads();
        if (t + 2 < 25) issue(t + 2, buf);
    }

    // epilogue 1: bias + relu + tf32-round -> h1T[n1][b]   (aliases x/w bufs, safe after sync)
#pragma unroll
    for (int mf = 0; mf < 4; mf++) {
        int n = wm * 64 + mf * 16 + g;
        float bi0 = smf[OFF_B1 + n], bi8 = smf[OFF_B1 + n + 8];
#pragma unroll
        for (int nf = 0; nf < 4; nf++) {
            int bc = wn * 32 + nf * 8 + 2 * q;
            smf[OFF_H1 + n * H1S + bc]           = tf32f(fmaxf(acc[mf][nf][0] + bi0, 0.f));
            smf[OFF_H1 + n * H1S + bc + 1]       = tf32f(fmaxf(acc[mf][nf][1] + bi0, 0.f));
            smf[OFF_H1 + (n + 8) * H1S + bc]     = tf32f(fmaxf(acc[mf][nf][2] + bi8, 0.f));
            smf[OFF_H1 + (n + 8) * H1S + bc + 1] = tf32f(fmaxf(acc[mf][nf][3] + bi8, 0.f));
        }
    }
    __syncthreads();

    // ---------------- GEMM2: [128 n2] x [256 k] x [128 b] ----------------
    float acc2[2][4][4];
#pragma unroll
    for (int a = 0; a < 2; a++)
#pragma unroll
        for (int b = 0; b < 4; b++)
#pragma unroll
            for (int c = 0; c < 4; c++) acc2[a][b][c] = 0.f;

#pragma unroll 4
    for (int s = 0; s < 32; s++) {
        uint32_t a[2][4];
#pragma unroll
        for (int mf = 0; mf < 2; mf++) {
            float4 v = g_w2p[((s * 8 + wm * 2 + mf) * 8 + g) * 4 + q];
            a[mf][0] = __float_as_uint(v.x); a[mf][1] = __float_as_uint(v.y);
            a[mf][2] = __float_as_uint(v.z); a[mf][3] = __float_as_uint(v.w);
        }
        uint32_t bb[4][2];
#pragma unroll
        for (int nf = 0; nf < 4; nf++) {
            int bc = wn * 32 + nf * 8 + g;
            int k = s * 8 + q;
            bb[nf][0] = __float_as_uint(smf[OFF_H1 + k * H1S + bc]);
            bb[nf][1] = __float_as_uint(smf[OFF_H1 + (k + 4) * H1S + bc]);
        }
#pragma unroll
        for (int mf = 0; mf < 2; mf++)
#pragma unroll
            for (int nf = 0; nf < 4; nf++)
                mma8(acc2[mf][nf], a[mf][0], a[mf][1], a[mf][2], a[mf][3],
                     bb[nf][0], bb[nf][1]);
    }

    // epilogue 2 -> h2T[n2][b]  (disjoint from h1T; no sync needed before writes)
#pragma unroll
    for (int mf = 0; mf < 2; mf++) {
        int n = wm * 32 + mf * 16 + g;
        float bi0 = smf[OFF_B2 + n], bi8 = smf[OFF_B2 + n + 8];
#pragma unroll
        for (int nf = 0; nf < 4; nf++) {
            int bc = wn * 32 + nf * 8 + 2 * q;
            smf[OFF_H2 + n * H2S + bc]           = tf32f(fmaxf(acc2[mf][nf][0] + bi0, 0.f));
            smf[OFF_H2 + n * H2S + bc + 1]       = tf32f(fmaxf(acc2[mf][nf][1] + bi0, 0.f));
            smf[OFF_H2 + (n + 8) * H2S + bc]     = tf32f(fmaxf(acc2[mf][nf][2] + bi8, 0.f));
            smf[OFF_H2 + (n + 8) * H2S + bc + 1] = tf32f(fmaxf(acc2[mf][nf][3] + bi8, 0.f));
        }
    }
    __syncthreads();

    // ---------------- GEMM3: [16 n3] x [128 k] x [128 b] ----------------
    float acc3[4] = {0.f, 0.f, 0.f, 0.f};
    const float4* W3s = (const float4*)(smf + OFF_W3);
#pragma unroll
    for (int s = 0; s < 16; s++) {
        float4 v = W3s[(s * 8 + g) * 4 + q];
        int k = s * 8 + q;
        int bc = w * 8 + g;
        uint32_t b0v = __float_as_uint(smf[OFF_H2 + k * H2S + bc]);
        uint32_t b1v = __float_as_uint(smf[OFF_H2 + (k + 4) * H2S + bc]);
        mma8(acc3, __float_as_uint(v.x), __float_as_uint(v.y),
                   __float_as_uint(v.z), __float_as_uint(v.w), b0v, b1v);
    }
    {
        int bc = w * 8 + 2 * q;
        float bi = smf[OFF_B3 + g];
        out[(size_t)(m0 + bc) * 10 + g]     = acc3[0] + bi;
        out[(size_t)(m0 + bc + 1) * 10 + g] = acc3[1] + bi;
        if (g + 8 < 10) {
            float bi8 = smf[OFF_B3 + g + 8];
            out[(size_t)(m0 + bc) * 10 + g + 8]     = acc3[2] + bi8;
            out[(size_t)(m0 + bc + 1) * 10 + g + 8] = acc3[3] + bi8;
        }
    }
}

// ---------------------------------------------------------------------------
extern "C" void kernel_launch(void* const* d_in, const int* in_sizes, int n_in,
                              void* d_out, int out_size) {
    const float* x    = (const float*)d_in[0];
    const float* conv = (const float*)d_in[1];
    const float* w1   = (const float*)d_in[2];
    const float* b1   = (const float*)d_in[3];
    const float* w2   = (const float*)d_in[4];
    const float* b2   = (const float*)d_in[5];
    const float* w3   = (const float*)d_in[6];
    const float* b3   = (const float*)d_in[7];
    float* out = (float*)d_out;

    prep_kernel<<<234, 256>>>(conv, w1, w2, w3);

    cudaFuncSetAttribute(fused_kernel, cudaFuncAttributeMaxDynamicSharedMemorySize,
                         SMEM_FLOATS * 4);
    fused_kernel<<<512, 512, SMEM_FLOATS * 4>>>(x, b1, b2, b3, out);
}